// round 2
// baseline (speedup 1.0000x reference)
#include <cuda_runtime.h>
#include <math.h>

// Problem constants (shapes fixed by setup_inputs)
#define H      1024
#define E      8
#define TOPK   2
#define NTOK   4096          // 2 * 2048
#define NSEL   (TOPK * NTOK) // 8192 selections, k-major order

// Scratch (device globals: allocation-free rule)
__device__ int   g_top1[NTOK];
__device__ int   g_top2[NTOK];
__device__ float g_p1[NTOK];
__device__ float g_p2[NTOK];

// ---------------------------------------------------------------------------
// Kernel 1: logits = x @ w_g^T, top-2 per token, 2-way softmax probs.
// One warp per token; w_g (8x1024 f32 = 32KB) staged in shared.
// ---------------------------------------------------------------------------
__global__ __launch_bounds__(256) void k_gate(const float* __restrict__ x,
                                              const float* __restrict__ wg,
                                              int N) {
    __shared__ float s_wg[E * H];   // 32 KB
    for (int i = threadIdx.x; i < E * H; i += blockDim.x)
        s_wg[i] = wg[i];
    __syncthreads();

    int warp = threadIdx.x >> 5;
    int lane = threadIdx.x & 31;
    int token = blockIdx.x * 8 + warp;
    if (token >= N) return;

    const float4* x4 = reinterpret_cast<const float4*>(x + (size_t)token * H);
    float acc[E];
    #pragma unroll
    for (int e = 0; e < E; e++) acc[e] = 0.f;

    #pragma unroll
    for (int c = 0; c < H / (32 * 4); c++) {           // 8 chunks of float4
        int idx4 = c * 32 + lane;
        float4 xv = x4[idx4];
        int base = idx4 * 4;
        #pragma unroll
        for (int e = 0; e < E; e++) {
            float4 wv = *reinterpret_cast<const float4*>(&s_wg[e * H + base]);
            acc[e] += xv.x * wv.x + xv.y * wv.y + xv.z * wv.z + xv.w * wv.w;
        }
    }
    #pragma unroll
    for (int e = 0; e < E; e++) {
        #pragma unroll
        for (int off = 16; off > 0; off >>= 1)
            acc[e] += __shfl_xor_sync(0xffffffffu, acc[e], off);
    }

    if (lane == 0) {
        // top-1 (lowest index wins ties via strict >)
        int   i1 = 0; float l1 = acc[0];
        #pragma unroll
        for (int e = 1; e < E; e++)
            if (acc[e] > l1) { l1 = acc[e]; i1 = e; }
        // top-2
        int   i2 = -1; float l2 = -INFINITY;
        #pragma unroll
        for (int e = 0; e < E; e++)
            if (e != i1 && acc[e] > l2) { l2 = acc[e]; i2 = e; }

        // softmax over {l1, l2} (rest of canvas is -inf)
        float e2 = expf(l2 - l1);          // l1 >= l2
        float inv = 1.0f / (1.0f + e2);
        g_top1[token] = i1;
        g_top2[token] = i2;
        g_p1[token]   = inv;
        g_p2[token]   = e2 * inv;
    }
}

// ---------------------------------------------------------------------------
// Kernel 2 (single block, 1024 threads): per-expert prefix ranks over the
// k-major selection sequence, capacity mask, scatter nonzeros + used_capacity.
// Each thread owns 8 consecutive selections.
// ---------------------------------------------------------------------------
__global__ __launch_bounds__(1024) void k_dispatch(float* __restrict__ out,
                                                   int N, int C) {
    const int tid = threadIdx.x;
    const int SEL_PER_THREAD = NSEL / 1024;   // 8

    __shared__ int s_scan[E][1024];           // 32 KB

    int   es[8];
    float ps[8];
    int   cnt[E];
    #pragma unroll
    for (int e = 0; e < E; e++) cnt[e] = 0;

    #pragma unroll
    for (int j = 0; j < SEL_PER_THREAD; j++) {
        int s = tid * SEL_PER_THREAD + j;
        int k = s >> 12;          // s / NTOK
        int n = s & (NTOK - 1);
        int e = k ? g_top2[n] : g_top1[n];
        es[j] = (n << 3) | e;     // pack token + expert
        ps[j] = k ? g_p2[n] : g_p1[n];
        cnt[e]++;
    }
    #pragma unroll
    for (int e = 0; e < E; e++) s_scan[e][tid] = cnt[e];
    __syncthreads();

    // Hillis-Steele inclusive scan over 1024 threads, all 8 experts at once
    for (int off = 1; off < 1024; off <<= 1) {
        int add[E];
        if (tid >= off) {
            #pragma unroll
            for (int e = 0; e < E; e++) add[e] = s_scan[e][tid - off];
        }
        __syncthreads();
        if (tid >= off) {
            #pragma unroll
            for (int e = 0; e < E; e++) s_scan[e][tid] += add[e];
        }
        __syncthreads();
    }

    int base[E];
    #pragma unroll
    for (int e = 0; e < E; e++)
        base[e] = s_scan[e][tid] - cnt[e];    // exclusive prefix

    // Output layout: [used_capacity(8)] [cb_weight(N*E*C)] [sec_mask(N*E*C)]
    float* cb  = out + E;
    float* msk = cb + (size_t)N * E * C;

    #pragma unroll
    for (int j = 0; j < SEL_PER_THREAD; j++) {
        int e = es[j] & 7;
        int n = es[j] >> 3;
        int rank = base[e]++;
        if (rank < C) {
            size_t idx = ((size_t)n * E + e) * C + rank;
            cb[idx]  = ps[j];
            msk[idx] = 1.0f;
        }
    }

    if (tid < E) {
        int total = s_scan[tid][1023];
        out[tid] = (float)(total < C ? total : C);
    }
}

// ---------------------------------------------------------------------------
extern "C" void kernel_launch(void* const* d_in, const int* in_sizes, int n_in,
                              void* d_out, int out_size) {
    const float* x  = (const float*)d_in[0];   // [2,2048,1024]
    const float* wg = (const float*)d_in[1];   // [8,1024]

    int N = in_sizes[0] / H;                           // 4096
    int cap = (int)(TOPK * 2.0 * N / E);               // 2048
    if (cap < 4) cap = 4;

    // Zero the whole (poisoned) output: dominated by DRAM write bandwidth.
    cudaMemsetAsync(d_out, 0, (size_t)out_size * sizeof(float), 0);

    k_gate<<<(N + 7) / 8, 256>>>(x, wg, N);
    k_dispatch<<<1, 1024>>>((float*)d_out, N, cap);
}

// round 3
// speedup vs baseline: 1.0121x; 1.0121x over previous
#include <cuda_runtime.h>
#include <math.h>

// Problem constants (shapes fixed by setup_inputs)
#define H      1024
#define E      8
#define TOPK   2
#define NTOK   4096          // 2 * 2048
#define NSEL   (TOPK * NTOK) // 8192 selections, k-major order

// Scratch (device globals: allocation-free rule)
__device__ int   g_top1[NTOK];
__device__ int   g_top2[NTOK];
__device__ float g_p1[NTOK];
__device__ float g_p2[NTOK];
__device__ int   g_sel_idx[NSEL];   // flat index into cb region, -1 = dropped
__device__ float g_sel_p[NSEL];
__device__ float g_used[E];

// ---------------------------------------------------------------------------
// Kernel 1: logits = x @ w_g^T, top-2 per token, 2-way softmax probs.
// One warp per token; w_g (8x1024 f32 = 32KB) staged in shared.
// ---------------------------------------------------------------------------
__global__ __launch_bounds__(256) void k_gate(const float* __restrict__ x,
                                              const float* __restrict__ wg,
                                              int N) {
    __shared__ float s_wg[E * H];   // 32 KB
    for (int i = threadIdx.x; i < E * H; i += blockDim.x)
        s_wg[i] = wg[i];
    __syncthreads();

    int warp = threadIdx.x >> 5;
    int lane = threadIdx.x & 31;
    int token = blockIdx.x * 8 + warp;
    if (token >= N) return;

    const float4* x4 = reinterpret_cast<const float4*>(x + (size_t)token * H);
    float acc[E];
    #pragma unroll
    for (int e = 0; e < E; e++) acc[e] = 0.f;

    #pragma unroll
    for (int c = 0; c < H / (32 * 4); c++) {           // 8 chunks of float4
        int idx4 = c * 32 + lane;
        float4 xv = x4[idx4];
        int base = idx4 * 4;
        #pragma unroll
        for (int e = 0; e < E; e++) {
            float4 wv = *reinterpret_cast<const float4*>(&s_wg[e * H + base]);
            acc[e] += xv.x * wv.x + xv.y * wv.y + xv.z * wv.z + xv.w * wv.w;
        }
    }
    #pragma unroll
    for (int e = 0; e < E; e++) {
        #pragma unroll
        for (int off = 16; off > 0; off >>= 1)
            acc[e] += __shfl_xor_sync(0xffffffffu, acc[e], off);
    }

    if (lane == 0) {
        // top-1 (lowest index wins ties via strict >)
        int   i1 = 0; float l1 = acc[0];
        #pragma unroll
        for (int e = 1; e < E; e++)
            if (acc[e] > l1) { l1 = acc[e]; i1 = e; }
        // top-2
        int   i2 = -1; float l2 = -INFINITY;
        #pragma unroll
        for (int e = 0; e < E; e++)
            if (e != i1 && acc[e] > l2) { l2 = acc[e]; i2 = e; }

        // softmax over {l1, l2} (rest of canvas is -inf)
        float e2 = expf(l2 - l1);          // l1 >= l2
        float inv = 1.0f / (1.0f + e2);
        g_top1[token] = i1;
        g_top2[token] = i2;
        g_p1[token]   = inv;
        g_p2[token]   = e2 * inv;
    }
}

// ---------------------------------------------------------------------------
// Kernel 2 (single block, 1024 threads): per-expert prefix ranks over the
// k-major selection sequence, capacity mask -> scratch (idx, prob) pairs.
// Runs concurrently with the big memset on another stream.
// ---------------------------------------------------------------------------
__global__ __launch_bounds__(1024) void k_rank(int N, int C) {
    const int tid = threadIdx.x;
    const int SEL_PER_THREAD = NSEL / 1024;   // 8

    __shared__ int s_scan[E][1024];           // 32 KB

    int   es[8];
    float ps[8];
    int   cnt[E];
    #pragma unroll
    for (int e = 0; e < E; e++) cnt[e] = 0;

    #pragma unroll
    for (int j = 0; j < SEL_PER_THREAD; j++) {
        int s = tid * SEL_PER_THREAD + j;
        int k = s >> 12;          // s / NTOK
        int n = s & (NTOK - 1);
        int e = k ? g_top2[n] : g_top1[n];
        es[j] = (n << 3) | e;     // pack token + expert
        ps[j] = k ? g_p2[n] : g_p1[n];
        cnt[e]++;
    }
    #pragma unroll
    for (int e = 0; e < E; e++) s_scan[e][tid] = cnt[e];
    __syncthreads();

    // Hillis-Steele inclusive scan over 1024 threads, all 8 experts at once
    for (int off = 1; off < 1024; off <<= 1) {
        int add[E];
        if (tid >= off) {
            #pragma unroll
            for (int e = 0; e < E; e++) add[e] = s_scan[e][tid - off];
        }
        __syncthreads();
        if (tid >= off) {
            #pragma unroll
            for (int e = 0; e < E; e++) s_scan[e][tid] += add[e];
        }
        __syncthreads();
    }

    int base[E];
    #pragma unroll
    for (int e = 0; e < E; e++)
        base[e] = s_scan[e][tid] - cnt[e];    // exclusive prefix

    #pragma unroll
    for (int j = 0; j < SEL_PER_THREAD; j++) {
        int s = tid * SEL_PER_THREAD + j;
        int e = es[j] & 7;
        int n = es[j] >> 3;
        int rank = base[e]++;
        // flat index into cb region [N, E, C]; fits in int (67M < 2^31)
        g_sel_idx[s] = (rank < C) ? ((n * E + e) * C + rank) : -1;
        g_sel_p[s]   = ps[j];
    }

    if (tid < E) {
        int total = s_scan[tid][1023];
        g_used[tid] = (float)(total < C ? total : C);
    }
}

// ---------------------------------------------------------------------------
// Kernel 3: tiny scatter after the memset — 8192 predicated pairs + 8 counts.
// ---------------------------------------------------------------------------
__global__ __launch_bounds__(1024) void k_scatter(float* __restrict__ out,
                                                  int N, int C) {
    int s = blockIdx.x * blockDim.x + threadIdx.x;
    float* cb  = out + E;
    float* msk = cb + (size_t)N * E * C;
    if (s < NSEL) {
        int idx = g_sel_idx[s];
        if (idx >= 0) {
            float p = g_sel_p[s];
            cb[idx]  = p;
            msk[idx] = 1.0f;
        }
    }
    if (blockIdx.x == 0 && threadIdx.x < E)
        out[threadIdx.x] = g_used[threadIdx.x];
}

// ---------------------------------------------------------------------------
extern "C" void kernel_launch(void* const* d_in, const int* in_sizes, int n_in,
                              void* d_out, int out_size) {
    const float* x  = (const float*)d_in[0];   // [2,2048,1024]
    const float* wg = (const float*)d_in[1];   // [8,1024]

    int N = in_sizes[0] / H;                           // 4096
    int cap = (int)(TOPK * 2.0 * N / E);               // 2048
    if (cap < 4) cap = 4;

    // Lazily create side stream + events (first call is the non-captured
    // correctness run, so creation never happens during graph capture).
    static cudaStream_t s2 = nullptr;
    static cudaEvent_t  evFork = nullptr, evJoin = nullptr;
    if (!s2) {
        cudaStreamCreateWithFlags(&s2, cudaStreamNonBlocking);
        cudaEventCreateWithFlags(&evFork, cudaEventDisableTiming);
        cudaEventCreateWithFlags(&evJoin, cudaEventDisableTiming);
    }

    // Fork: gate + rank on s2, concurrent with the big zeroing memset on the
    // capture stream. Join before the scatter (which writes into d_out).
    cudaEventRecord(evFork, 0);
    cudaStreamWaitEvent(s2, evFork, 0);

    k_gate<<<(N + 7) / 8, 256, 0, s2>>>(x, wg, N);
    k_rank<<<1, 1024, 0, s2>>>(N, cap);
    cudaEventRecord(evJoin, s2);

    // Zero the whole (poisoned) output: DRAM-write-bound, ~537 MB.
    cudaMemsetAsync(d_out, 0, (size_t)out_size * sizeof(float), 0);

    cudaStreamWaitEvent(0, evJoin, 0);
    k_scatter<<<NSEL / 1024, 1024>>>((float*)d_out, N, cap);
}

// round 4
// speedup vs baseline: 1.0441x; 1.0316x over previous
#include <cuda_runtime.h>
#include <math.h>

// Problem constants (shapes fixed by setup_inputs)
#define H      1024
#define E      8
#define TOPK   2
#define NTOK   4096          // 2 * 2048
#define NSEL   (TOPK * NTOK) // 8192 selections, k-major order
#define CAP    2048          // floor(2*2.0*4096/8)

#define GATE_BLOCKS 32
#define ZGRID       592      // 148 SMs * 4 blocks
#define ZTHREADS    256
#define TOTAL_F     134217736u            // 8 + 2*N*E*C floats
#define TOTAL4      33554434u             // TOTAL_F / 4
#define CH4         8192u                 // float4 per chunk (128 KB)
#define NCHUNK      4097u                 // ceil(TOTAL4 / CH4)

// Scratch (device globals: allocation-free rule)
__device__ int   g_top1[NTOK];
__device__ int   g_top2[NTOK];
__device__ float g_p1[NTOK];
__device__ float g_p2[NTOK];
__device__ int   g_sel_idx[NSEL];   // flat index into cb region, -1 = dropped
__device__ float g_sel_p[NSEL];
__device__ float g_used[E];
__device__ unsigned int g_chunk = 0;   // reset by k_scatter each execution

// ---------------------------------------------------------------------------
// Fused kernel: all blocks zero the output via dynamic chunk-grabbing;
// blocks 0..31 first compute the gating GEMV + top-2 + softmax (hidden under
// the DRAM-bound zeroing done by the other 560 blocks).
// ---------------------------------------------------------------------------
__global__ __launch_bounds__(ZTHREADS) void k_zero_gate(float* __restrict__ out,
                                                        const float* __restrict__ x,
                                                        const float* __restrict__ wg) {
    __shared__ float s_wg[E * H];   // 32 KB

    if (blockIdx.x < GATE_BLOCKS) {
        // ---- gate: 128 tokens per block, 16 per warp, 4 at a time ----
        for (int i = threadIdx.x; i < E * H; i += ZTHREADS)
            s_wg[i] = wg[i];
        __syncthreads();

        int warp = threadIdx.x >> 5;
        int lane = threadIdx.x & 31;

        for (int grp = 0; grp < 4; grp++) {
            int t0 = ((blockIdx.x * 8 + warp) * 4 + grp) * 4;  // 4 consecutive tokens
            float acc[4][E];
            #pragma unroll
            for (int t = 0; t < 4; t++)
                #pragma unroll
                for (int e = 0; e < E; e++) acc[t][e] = 0.f;

            #pragma unroll
            for (int c = 0; c < H / 128; c++) {          // 8 chunks of 32*float4
                int idx4 = c * 32 + lane;
                float4 xv[4];
                #pragma unroll
                for (int t = 0; t < 4; t++)
                    xv[t] = reinterpret_cast<const float4*>(x + (size_t)(t0 + t) * H)[idx4];
                int base = idx4 * 4;
                #pragma unroll
                for (int e = 0; e < E; e++) {
                    float4 wv = *reinterpret_cast<const float4*>(&s_wg[e * H + base]);
                    #pragma unroll
                    for (int t = 0; t < 4; t++)
                        acc[t][e] += xv[t].x * wv.x + xv[t].y * wv.y
                                   + xv[t].z * wv.z + xv[t].w * wv.w;
                }
            }
            #pragma unroll
            for (int t = 0; t < 4; t++)
                #pragma unroll
                for (int e = 0; e < E; e++)
                    #pragma unroll
                    for (int off = 16; off > 0; off >>= 1)
                        acc[t][e] += __shfl_xor_sync(0xffffffffu, acc[t][e], off);

            if (lane < 4) {
                int token = t0 + lane;
                float l[E];
                #pragma unroll
                for (int e = 0; e < E; e++) l[e] = acc[lane][e];
                int   i1 = 0; float l1 = l[0];
                #pragma unroll
                for (int e = 1; e < E; e++)
                    if (l[e] > l1) { l1 = l[e]; i1 = e; }
                int   i2 = -1; float l2 = -INFINITY;
                #pragma unroll
                for (int e = 0; e < E; e++)
                    if (e != i1 && l[e] > l2) { l2 = l[e]; i2 = e; }
                float e2 = expf(l2 - l1);
                float inv = 1.0f / (1.0f + e2);
                g_top1[token] = i1;
                g_top2[token] = i2;
                g_p1[token]   = inv;
                g_p2[token]   = e2 * inv;
            }
        }
    }

    // ---- zeroing: dynamic chunk grab, streaming float4 stores ----
    __shared__ unsigned int s_c;
    float4* out4 = reinterpret_cast<float4*>(out);
    const float4 z4 = make_float4(0.f, 0.f, 0.f, 0.f);
    for (;;) {
        if (threadIdx.x == 0) s_c = atomicAdd(&g_chunk, 1u);
        __syncthreads();
        unsigned int c = s_c;
        __syncthreads();
        if (c >= NCHUNK) break;
        unsigned int base4 = c * CH4;
        #pragma unroll 4
        for (unsigned int i = threadIdx.x; i < CH4; i += ZTHREADS) {
            unsigned int idx = base4 + i;
            if (idx < TOTAL4) __stcs(&out4[idx], z4);
        }
    }
}

// ---------------------------------------------------------------------------
// Rank kernel: 8 warps, ballot-based per-expert prefix ranks, two passes.
// ---------------------------------------------------------------------------
__global__ __launch_bounds__(256) void k_rank(int C) {
    const int tid  = threadIdx.x;
    const int warp = tid >> 5;
    const int lane = tid & 31;
    const unsigned lt = (1u << lane) - 1u;

    __shared__ int s_tot[8][E];
    __shared__ int s_off[8][E];

    // Pass 1: per-warp per-expert counts over 1024 consecutive selections.
    int run[E];
    #pragma unroll
    for (int e = 0; e < E; e++) run[e] = 0;
    for (int i = 0; i < 32; i++) {
        int s = warp * 1024 + i * 32 + lane;
        int n = s & (NTOK - 1);
        int e = (s >> 12) ? g_top2[n] : g_top1[n];
        #pragma unroll
        for (int eid = 0; eid < E; eid++) {
            unsigned b = __ballot_sync(0xffffffffu, e == eid);
            run[eid] += __popc(b);
        }
    }
    if (lane < E) {
        int v = 0;
        #pragma unroll
        for (int eid = 0; eid < E; eid++) if (lane == eid) v = run[eid];
        s_tot[warp][lane] = v;
    }
    __syncthreads();

    // Cross-warp exclusive scan (64 values) + grand totals.
    if (tid < 64) {
        int w = tid >> 3, e = tid & 7;
        int o = 0;
        for (int wp = 0; wp < w; wp++) o += s_tot[wp][e];
        s_off[w][e] = o;
        if (w == 7) {
            int total = o + s_tot[7][e];
            g_used[e] = (float)(total < C ? total : C);
        }
    }
    __syncthreads();

    // Pass 2: replay, emit (flat index, prob).
    #pragma unroll
    for (int e = 0; e < E; e++) run[e] = 0;
    for (int i = 0; i < 32; i++) {
        int s = warp * 1024 + i * 32 + lane;
        int n = s & (NTOK - 1);
        int k = s >> 12;
        int e = k ? g_top2[n] : g_top1[n];
        float p = k ? g_p2[n] : g_p1[n];
        int myrank = 0;
        #pragma unroll
        for (int eid = 0; eid < E; eid++) {
            unsigned b = __ballot_sync(0xffffffffu, e == eid);
            if (e == eid) myrank = run[eid] + __popc(b & lt);
            run[eid] += __popc(b);
        }
        int rank = s_off[warp][e] + myrank;
        g_sel_idx[s] = (rank < C) ? ((n * E + e) * C + rank) : -1;
        g_sel_p[s]   = p;
    }
}

// ---------------------------------------------------------------------------
// Scatter kernel: 8192 predicated pairs + 8 counts; resets chunk counter.
// ---------------------------------------------------------------------------
__global__ __launch_bounds__(1024) void k_scatter(float* __restrict__ out,
                                                  int N, int C) {
    int s = blockIdx.x * blockDim.x + threadIdx.x;
    float* cb  = out + E;
    float* msk = cb + (size_t)N * E * C;
    if (s < NSEL) {
        int idx = g_sel_idx[s];
        if (idx >= 0) {
            float p = g_sel_p[s];
            cb[idx]  = p;
            msk[idx] = 1.0f;
        }
    }
    if (blockIdx.x == 0 && threadIdx.x == 0)
        g_chunk = 0;                       // arm next execution
    if (blockIdx.x == 0 && threadIdx.x < E)
        out[threadIdx.x] = g_used[threadIdx.x];
}

// ---------------------------------------------------------------------------
extern "C" void kernel_launch(void* const* d_in, const int* in_sizes, int n_in,
                              void* d_out, int out_size) {
    const float* x  = (const float*)d_in[0];   // [2,2048,1024]
    const float* wg = (const float*)d_in[1];   // [8,1024]

    int N = in_sizes[0] / H;                           // 4096
    int cap = (int)(TOPK * 2.0 * N / E);               // 2048
    if (cap < 4) cap = 4;

    k_zero_gate<<<ZGRID, ZTHREADS>>>((float*)d_out, x, wg);
    k_rank<<<1, 256>>>(cap);
    k_scatter<<<NSEL / 1024, 1024>>>((float*)d_out, N, cap);
}